// round 4
// baseline (speedup 1.0000x reference)
#include <cuda_runtime.h>
#include <math.h>

#define B_ 2
#define H_ 8
#define NSEQ 2048
#define DDIM 64
#define BH (B_*H_)
#define ROWS 8
#define NTHREADS 256
#define TILE_M 64
#define PAD 68
#define NTILES (NSEQ/TILE_M)      // 32
#define NWORDS 3126               // ceil(100001/32)
#define TILE_F (TILE_M*PAD)       // 4352 floats per tile buffer

typedef unsigned long long u64;

__device__ __forceinline__ u64 pk2(float x, float y) {
    u64 u; asm("mov.b64 %0,{%1,%2};" : "=l"(u) : "f"(x), "f"(y)); return u;
}
__device__ __forceinline__ float2 up2(u64 u) {
    float2 r; asm("mov.b64 {%0,%1},%2;" : "=f"(r.x), "=f"(r.y) : "l"(u)); return r;
}
__device__ __forceinline__ void fma2(u64 &d, u64 a, u64 b) {
    asm("fma.rn.f32x2 %0,%1,%2,%3;" : "=l"(d) : "l"(a), "l"(b), "l"(d));
}

// ============================================================================
// Kernel A: scores -> rowmax -> exp/round -> distinct-sum denom -> attn_p
// smem ~100KB -> 2 CTAs/SM. Bitmap aliases the K-tile buffers (phase-exclusive).
// ============================================================================
__global__ __launch_bounds__(NTHREADS, 2)
void sdpa_scores_kernel(const float* __restrict__ q,
                        const float* __restrict__ k,
                        float* __restrict__ attn_out) {
    extern __shared__ float sm[];
    float* s    = sm;                       // [ROWS][NSEQ]  64KB
    float* qs   = s + ROWS*NSEQ;            // [ROWS][DDIM]  2KB
    float* tile = qs + ROWS*DDIM;           // 2 x [TILE_M][PAD]  ~34KB
    unsigned* bmp = (unsigned*)tile;        // aliased: used only in phase 4
    u64* rowSum = (u64*)(tile + 2*TILE_F);  // [ROWS]
    float* scale = (float*)(rowSum + ROWS); // [ROWS]

    const int tid  = threadIdx.x;
    const int w    = tid >> 5;
    const int lane = tid & 31;
    const int kg   = w & 1;          // k-col half within tile
    const int qg   = (w >> 1) & 1;   // q-row group of 4
    const int tp   = w >> 2;         // tile parity within pair
    const int bh   = blockIdx.y;
    const int row0 = blockIdx.x * ROWS;
    const size_t base = (size_t)bh * NSEQ * DDIM;

    // ---- load Q (pre-scaled by 1/T) ----
    for (int i = tid; i < ROWS*DDIM; i += NTHREADS)
        qs[i] = q[base + (size_t)row0*DDIM + i] * 0.125f;

    // ---- fill K tile pair 0 (tiles 0 and 1) ----
    {
        const float4* kg4 = (const float4*)(k + base);
        #pragma unroll
        for (int j = 0; j < 8; j++) {
            int idx = tid + j*NTHREADS;          // 0..2047 float4 over 2 tiles
            int tb = idx >> 10, wi = idx & 1023;
            *(float4*)&tile[tb*TILE_F + (wi>>4)*PAD + (wi&15)*4] = kg4[idx];
        }
    }
    __syncthreads();

    // ---- phase 1: S = (Q/T) @ K^T ; warp computes 4 q-rows x 32 k-cols ----
    const float4* qs4 = (const float4*)qs;
    for (int t2 = 0; t2 < NTILES/2; t2++) {
        float4 pre[8];
        if (t2 + 1 < NTILES/2) {
            const float4* kg4 = (const float4*)(k + base + (size_t)(2*t2+2)*TILE_M*DDIM);
            #pragma unroll
            for (int j = 0; j < 8; j++) pre[j] = kg4[tid + j*NTHREADS];
        }
        const float4* krow = (const float4*)&tile[tp*TILE_F + (kg*32 + lane)*PAD];
        u64 a0 = 0, a1 = 0, a2 = 0, a3 = 0;
        #pragma unroll
        for (int d4 = 0; d4 < 16; d4++) {
            float4 kv = krow[d4];
            u64 kl = pk2(kv.x, kv.y), kh = pk2(kv.z, kv.w);
            float4 qv;
            qv = qs4[(4*qg+0)*16 + d4]; fma2(a0, pk2(qv.x,qv.y), kl); fma2(a0, pk2(qv.z,qv.w), kh);
            qv = qs4[(4*qg+1)*16 + d4]; fma2(a1, pk2(qv.x,qv.y), kl); fma2(a1, pk2(qv.z,qv.w), kh);
            qv = qs4[(4*qg+2)*16 + d4]; fma2(a2, pk2(qv.x,qv.y), kl); fma2(a2, pk2(qv.z,qv.w), kh);
            qv = qs4[(4*qg+3)*16 + d4]; fma2(a3, pk2(qv.x,qv.y), kl); fma2(a3, pk2(qv.z,qv.w), kh);
        }
        int m = (2*t2 + tp)*TILE_M + kg*32 + lane;
        float2 f;
        f = up2(a0); s[(4*qg+0)*NSEQ + m] = f.x + f.y;
        f = up2(a1); s[(4*qg+1)*NSEQ + m] = f.x + f.y;
        f = up2(a2); s[(4*qg+2)*NSEQ + m] = f.x + f.y;
        f = up2(a3); s[(4*qg+3)*NSEQ + m] = f.x + f.y;
        __syncthreads();
        if (t2 + 1 < NTILES/2) {
            #pragma unroll
            for (int j = 0; j < 8; j++) {
                int idx = tid + j*NTHREADS;
                int tb = idx >> 10, wi = idx & 1023;
                *(float4*)&tile[tb*TILE_F + (wi>>4)*PAD + (wi&15)*4] = pre[j];
            }
            __syncthreads();
        }
    }

    // ---- phase 2+3: warp w owns row w: max, exp, round-to-int ----
    {
        float mx = -INFINITY;
        for (int m = lane; m < NSEQ; m += 32) mx = fmaxf(mx, s[w*NSEQ + m]);
        #pragma unroll
        for (int o = 16; o > 0; o >>= 1) mx = fmaxf(mx, __shfl_xor_sync(0xffffffffu, mx, o));
        for (int m = lane; m < NSEQ; m += 32)
            s[w*NSEQ + m] = rintf(expf(s[w*NSEQ + m] - mx) * 100000.0f);
    }

    // ---- init bitmap (aliased over tile buffers) + row sums ----
    __syncthreads();
    for (int i = tid; i < NWORDS; i += NTHREADS) bmp[i] = 0u;
    if (tid < ROWS) rowSum[tid] = 0ull;
    __syncthreads();

    // ---- phase 4: distinct-sum denominator; warp-dedup via match_any ----
    for (int r = 0; r < ROWS; r++) {
        u64 local = 0ull;
        for (int m = tid; m < NSEQ; m += NTHREADS) {
            int ri = (int)s[r*NSEQ + m];
            unsigned peers = __match_any_sync(0xffffffffu, ri);
            if (ri != 0 && (int)(__ffs(peers) - 1) == lane) {
                unsigned bit = 1u << (ri & 31);
                unsigned old = atomicOr(&bmp[ri >> 5], bit);
                if (!(old & bit)) local += (unsigned)ri;
            }
        }
        #pragma unroll
        for (int o = 16; o > 0; o >>= 1) local += __shfl_xor_sync(0xffffffffu, local, o);
        if (lane == 0 && local) atomicAdd(&rowSum[r], local);
        __syncthreads();
        for (int m = tid; m < NSEQ; m += NTHREADS)      // clear touched words
            bmp[((int)s[r*NSEQ + m]) >> 5] = 0u;
        __syncthreads();
    }
    if (tid < ROWS) scale[tid] = 1.0f / (float)rowSum[tid];
    __syncthreads();

    // ---- phase 5: write attn_p (warp w -> row w), coalesced float4 ----
    {
        float sc = scale[w];
        float4* dst4 = (float4*)(attn_out + ((size_t)bh*NSEQ + row0 + w) * NSEQ);
        const float4* src4 = (const float4*)&s[w*NSEQ];
        for (int i = lane; i < NSEQ/4; i += 32) {
            float4 vv = src4[i];
            vv.x *= sc; vv.y *= sc; vv.z *= sc; vv.w *= sc;
            dst4[i] = vv;
        }
    }
}

// ============================================================================
// Kernel B: out = attn_p @ V   (register-tiled GEMM, 64q x 64d per block)
// ============================================================================
#define PADB 68
__global__ __launch_bounds__(256)
void pv_kernel(const float* __restrict__ attn,
               const float* __restrict__ v,
               float* __restrict__ out) {
    __shared__ float Pt[TILE_M * PADB];   // [64 q][64 k]
    __shared__ float Vt[TILE_M * PADB];   // [64 k][64 d]

    const int tid = threadIdx.x;
    const int tx = tid & 15;       // d-group: cols 4*tx..4*tx+3
    const int ty = tid >> 4;       // q-group: rows 4*ty..4*ty+3
    const int bh = blockIdx.y;
    const int row0 = blockIdx.x * TILE_M;
    const size_t abase = ((size_t)bh * NSEQ + row0) * NSEQ;
    const size_t vbase = (size_t)bh * NSEQ * DDIM;

    u64 acc[4][2];
    #pragma unroll
    for (int i = 0; i < 4; i++) { acc[i][0] = 0ull; acc[i][1] = 0ull; }

    for (int t = 0; t < NTILES; t++) {
        #pragma unroll
        for (int j = 0; j < 4; j++) {
            int idx = tid + j*256;             // 0..1023
            int rr = idx >> 4, c4 = idx & 15;
            *(float4*)&Pt[rr*PADB + c4*4] =
                *(const float4*)&attn[abase + (size_t)rr*NSEQ + t*TILE_M + c4*4];
            *(float4*)&Vt[rr*PADB + c4*4] =
                *(const float4*)&v[vbase + (size_t)(t*TILE_M + rr)*DDIM + c4*4];
        }
        __syncthreads();
        #pragma unroll 4
        for (int kk = 0; kk < TILE_M; kk++) {
            float4 vv = *(const float4*)&Vt[kk*PADB + tx*4];
            u64 vlo = pk2(vv.x, vv.y), vhi = pk2(vv.z, vv.w);
            #pragma unroll
            for (int i = 0; i < 4; i++) {
                float p = Pt[(ty*4 + i)*PADB + kk];
                u64 pp = pk2(p, p);
                fma2(acc[i][0], pp, vlo);
                fma2(acc[i][1], pp, vhi);
            }
        }
        __syncthreads();
    }

    #pragma unroll
    for (int i = 0; i < 4; i++) {
        float2 lo = up2(acc[i][0]), hi = up2(acc[i][1]);
        float4 r; r.x = lo.x; r.y = lo.y; r.z = hi.x; r.w = hi.y;
        *(float4*)&out[((size_t)bh*NSEQ + row0 + ty*4 + i)*DDIM + tx*4] = r;
    }
}

extern "C" void kernel_launch(void* const* d_in, const int* in_sizes, int n_in,
                              void* d_out, int out_size) {
    const float* q = (const float*)d_in[0];
    const float* k = (const float*)d_in[1];
    const float* v = (const float*)d_in[2];
    float* out = (float*)d_out;                                 // [B,H,N,D]
    float* attn_out = out + (size_t)B_ * H_ * NSEQ * DDIM;      // [B,H,N,N]

    const int smemA = (ROWS*NSEQ + ROWS*DDIM + 2*TILE_F) * 4 + ROWS*8 + ROWS*4;
    cudaFuncSetAttribute(sdpa_scores_kernel,
                         cudaFuncAttributeMaxDynamicSharedMemorySize, smemA);

    dim3 gridA(NSEQ / ROWS, BH);
    sdpa_scores_kernel<<<gridA, NTHREADS, smemA>>>(q, k, attn_out);

    dim3 gridB(NSEQ / TILE_M, BH);
    pv_kernel<<<gridB, 256>>>(attn_out, v, out);
}

// round 5
// speedup vs baseline: 1.1560x; 1.1560x over previous
#include <cuda_runtime.h>
#include <math.h>

#define B_ 2
#define H_ 8
#define NSEQ 2048
#define DDIM 64
#define BH (B_*H_)
#define ROWS 8
#define NTHREADS 256
#define TILE_M 64
#define PAD 68
#define NTILES (NSEQ/TILE_M)      // 32
#define NWORDS 3126               // ceil(100001/32)
#define TILE_F (TILE_M*PAD)       // 4352 floats

typedef unsigned long long u64;

__device__ __forceinline__ u64 pk2(float x, float y) {
    u64 u; asm("mov.b64 %0,{%1,%2};" : "=l"(u) : "f"(x), "f"(y)); return u;
}
__device__ __forceinline__ float2 up2(u64 u) {
    float2 r; asm("mov.b64 {%0,%1},%2;" : "=f"(r.x), "=f"(r.y) : "l"(u)); return r;
}
__device__ __forceinline__ void fma2(u64 &d, u64 a, u64 b) {
    asm("fma.rn.f32x2 %0,%1,%2,%3;" : "=l"(d) : "l"(a), "l"(b), "l"(d));
}
__device__ __forceinline__ void cpa16(unsigned dst, const void* src) {
    asm volatile("cp.async.cg.shared.global [%0], [%1], 16;" :: "r"(dst), "l"(src));
}
__device__ __forceinline__ void cp_commit() { asm volatile("cp.async.commit_group;"); }
__device__ __forceinline__ void cp_wait0()  { asm volatile("cp.async.wait_group 0;" ::: "memory"); }
__device__ __forceinline__ void cp_wait1()  { asm volatile("cp.async.wait_group 1;" ::: "memory"); }

// ============================================================================
// Kernel A: scores -> rowmax -> exp/round -> distinct-sum denom -> attn_p
// ~100.5KB smem, low regs via cp.async -> 2 CTAs/SM.
// ============================================================================
__global__ __launch_bounds__(NTHREADS, 2)
void sdpa_scores_kernel(const float* __restrict__ q,
                        const float* __restrict__ k,
                        float* __restrict__ attn_out) {
    extern __shared__ float sm[];
    float* s    = sm;                       // [ROWS][NSEQ]  64KB
    float* qs   = s + ROWS*NSEQ;            // [ROWS][DDIM]  2KB
    float* tile = qs + ROWS*DDIM;           // 2 x [TILE_M][PAD]  ~34KB
    unsigned* bmp = (unsigned*)tile;        // aliased over tile (phase 4 only)
    u64* rowSum = (u64*)(tile + 2*TILE_F);
    float* scale = (float*)(rowSum + ROWS);

    const int tid  = threadIdx.x;
    const int w    = tid >> 5;
    const int lane = tid & 31;
    const int kg   = w & 1;          // k-col half
    const int qg   = (w >> 1) & 1;   // q-row group of 4
    const int tp   = w >> 2;         // tile parity within pair
    const int bh   = blockIdx.y;
    const int row0 = blockIdx.x * ROWS;
    const size_t base = (size_t)bh * NSEQ * DDIM;
    const unsigned tileu = (unsigned)__cvta_generic_to_shared(tile);

    // ---- load Q (pre-scaled by 1/T) ----
    for (int i = tid; i < ROWS*DDIM; i += NTHREADS)
        qs[i] = q[base + (size_t)row0*DDIM + i] * 0.125f;
    if (tid < ROWS) rowSum[tid] = 0ull;

    // ---- phase 1: S = (Q/T) @ K^T ; per pair: cp.async load, then compute ----
    const float4* qs4 = (const float4*)qs;
    for (int t2 = 0; t2 < NTILES/2; t2++) {
        const float4* kg4 = (const float4*)(k + base + (size_t)(2*t2)*TILE_M*DDIM);
        #pragma unroll
        for (int j = 0; j < 8; j++) {
            int idx = tid + j*NTHREADS;          // 0..2047 float4 over 2 tiles
            int tb = idx >> 10, wi = idx & 1023;
            cpa16(tileu + 4u*(tb*TILE_F + (wi>>4)*PAD + (wi&15)*4), kg4 + idx);
        }
        cp_commit(); cp_wait0();
        __syncthreads();

        const float4* krow = (const float4*)&tile[tp*TILE_F + (kg*32 + lane)*PAD];
        u64 a0 = 0, a1 = 0, a2 = 0, a3 = 0;
        #pragma unroll
        for (int d4 = 0; d4 < 16; d4++) {
            float4 kv = krow[d4];
            u64 kl = pk2(kv.x, kv.y), kh = pk2(kv.z, kv.w);
            float4 qv;
            qv = qs4[(4*qg+0)*16 + d4]; fma2(a0, pk2(qv.x,qv.y), kl); fma2(a0, pk2(qv.z,qv.w), kh);
            qv = qs4[(4*qg+1)*16 + d4]; fma2(a1, pk2(qv.x,qv.y), kl); fma2(a1, pk2(qv.z,qv.w), kh);
            qv = qs4[(4*qg+2)*16 + d4]; fma2(a2, pk2(qv.x,qv.y), kl); fma2(a2, pk2(qv.z,qv.w), kh);
            qv = qs4[(4*qg+3)*16 + d4]; fma2(a3, pk2(qv.x,qv.y), kl); fma2(a3, pk2(qv.z,qv.w), kh);
        }
        int m = (2*t2 + tp)*TILE_M + kg*32 + lane;
        float2 f;
        f = up2(a0); s[(4*qg+0)*NSEQ + m] = f.x + f.y;
        f = up2(a1); s[(4*qg+1)*NSEQ + m] = f.x + f.y;
        f = up2(a2); s[(4*qg+2)*NSEQ + m] = f.x + f.y;
        f = up2(a3); s[(4*qg+3)*NSEQ + m] = f.x + f.y;
        __syncthreads();
    }

    // ---- phase 2+3: warp w owns row w: max, exp, round-to-int (float4) ----
    {
        float4* srow4 = (float4*)&s[w*NSEQ];
        float mx = -INFINITY;
        for (int i = lane; i < NSEQ/4; i += 32) {
            float4 vv = srow4[i];
            mx = fmaxf(mx, fmaxf(fmaxf(vv.x, vv.y), fmaxf(vv.z, vv.w)));
        }
        #pragma unroll
        for (int o = 16; o > 0; o >>= 1) mx = fmaxf(mx, __shfl_xor_sync(0xffffffffu, mx, o));
        for (int i = lane; i < NSEQ/4; i += 32) {
            float4 vv = srow4[i];
            vv.x = rintf(expf(vv.x - mx) * 100000.0f);
            vv.y = rintf(expf(vv.y - mx) * 100000.0f);
            vv.z = rintf(expf(vv.z - mx) * 100000.0f);
            vv.w = rintf(expf(vv.w - mx) * 100000.0f);
            srow4[i] = vv;
        }
    }
    __syncthreads();

    // ---- init bitmap (aliased over tile buffers) ----
    for (int i = tid; i < NWORDS; i += NTHREADS) bmp[i] = 0u;
    __syncthreads();

    // ---- phase 4: distinct-sum denominator; warp-dedup via match_any ----
    for (int r = 0; r < ROWS; r++) {
        const float4* row4 = (const float4*)&s[r*NSEQ];
        u64 local = 0ull;
        #pragma unroll
        for (int j = 0; j < 2; j++) {
            float4 vv = row4[tid*2 + j];
            float vals[4] = {vv.x, vv.y, vv.z, vv.w};
            #pragma unroll
            for (int e = 0; e < 4; e++) {
                int ri = (int)vals[e];
                unsigned peers = __match_any_sync(0xffffffffu, ri);
                if (ri != 0 && (int)(__ffs(peers) - 1) == lane) {
                    unsigned bit = 1u << (ri & 31);
                    unsigned old = atomicOr(&bmp[ri >> 5], bit);
                    if (!(old & bit)) local += (unsigned)ri;
                }
            }
        }
        #pragma unroll
        for (int o = 16; o > 0; o >>= 1) local += __shfl_xor_sync(0xffffffffu, local, o);
        if (lane == 0 && local) atomicAdd(&rowSum[r], local);
        __syncthreads();
        #pragma unroll
        for (int j = 0; j < 2; j++) {        // clear touched words
            float4 vv = row4[tid*2 + j];
            bmp[((int)vv.x) >> 5] = 0u; bmp[((int)vv.y) >> 5] = 0u;
            bmp[((int)vv.z) >> 5] = 0u; bmp[((int)vv.w) >> 5] = 0u;
        }
        __syncthreads();
    }
    if (tid < ROWS) scale[tid] = 1.0f / (float)rowSum[tid];
    __syncthreads();

    // ---- phase 5: write attn_p (warp w -> row w), coalesced float4 ----
    {
        float sc = scale[w];
        float4* dst4 = (float4*)(attn_out + ((size_t)bh*NSEQ + row0 + w) * NSEQ);
        const float4* src4 = (const float4*)&s[w*NSEQ];
        for (int i = lane; i < NSEQ/4; i += 32) {
            float4 vv = src4[i];
            vv.x *= sc; vv.y *= sc; vv.z *= sc; vv.w *= sc;
            dst4[i] = vv;
        }
    }
}

// ============================================================================
// Kernel B: out = attn_p @ V. 128q x 64d block, 8q x 4d per thread,
// cp.async double-buffered. 256 CTAs, 2/SM -> one wave.
// ============================================================================
#define PADB 68
#define QB 128
#define STAGE_F (QB*PADB + TILE_M*PADB)   // Pt + Vt floats per stage

__global__ __launch_bounds__(256, 2)
void pv_kernel(const float* __restrict__ attn,
               const float* __restrict__ v,
               float* __restrict__ out) {
    extern __shared__ float smb[];
    // stage layout: [Pt 128x68][Vt 64x68] x2
    const int tid = threadIdx.x;
    const int tx = tid & 15;       // d-group: cols 4*tx..4*tx+3
    const int ty = tid >> 4;       // q-group: rows 8*ty..8*ty+7
    const int bh = blockIdx.y;
    const int row0 = blockIdx.x * QB;
    const size_t abase = ((size_t)bh * NSEQ + row0) * NSEQ;
    const size_t vbase = (size_t)bh * NSEQ * DDIM;
    const unsigned smbu = (unsigned)__cvta_generic_to_shared(smb);

    // per-stage async load of Pt (2048 f4) + Vt (1024 f4): 12 cp.async/thread
    auto issue_stage = [&](int t, int buf) {
        unsigned pbase = smbu + 4u*buf*STAGE_F;
        unsigned vbse  = pbase + 4u*QB*PADB;
        const float4* ag = (const float4*)(attn + abase + (size_t)t*TILE_M);
        const float4* vg = (const float4*)(v + vbase + (size_t)t*TILE_M*DDIM);
        #pragma unroll
        for (int j = 0; j < 8; j++) {
            int idx = tid + j*256;            // 0..2047
            int rr = idx >> 4, c4 = idx & 15;
            cpa16(pbase + 4u*(rr*PADB + c4*4),
                  (const void*)(ag + (size_t)rr*(NSEQ/4) + c4));
        }
        #pragma unroll
        for (int j = 0; j < 4; j++) {
            int idx = tid + j*256;            // 0..1023
            int rr = idx >> 4, c4 = idx & 15;
            cpa16(vbse + 4u*(rr*PADB + c4*4), (const void*)(vg + idx));
        }
        cp_commit();
    };

    u64 acc[8][2];
    #pragma unroll
    for (int i = 0; i < 8; i++) { acc[i][0] = 0ull; acc[i][1] = 0ull; }

    issue_stage(0, 0);
    for (int t = 0; t < NTILES; t++) {
        if (t + 1 < NTILES) { issue_stage(t + 1, (t + 1) & 1); cp_wait1(); }
        else cp_wait0();
        __syncthreads();
        const float* Pt = smb + (t & 1)*STAGE_F;
        const float* Vt = Pt + QB*PADB;
        #pragma unroll 4
        for (int k4 = 0; k4 < TILE_M/4; k4++) {
            float4 v0 = *(const float4*)&Vt[(k4*4+0)*PADB + tx*4];
            float4 v1 = *(const float4*)&Vt[(k4*4+1)*PADB + tx*4];
            float4 v2 = *(const float4*)&Vt[(k4*4+2)*PADB + tx*4];
            float4 v3 = *(const float4*)&Vt[(k4*4+3)*PADB + tx*4];
            u64 v0l = pk2(v0.x,v0.y), v0h = pk2(v0.z,v0.w);
            u64 v1l = pk2(v1.x,v1.y), v1h = pk2(v1.z,v1.w);
            u64 v2l = pk2(v2.x,v2.y), v2h = pk2(v2.z,v2.w);
            u64 v3l = pk2(v3.x,v3.y), v3h = pk2(v3.z,v3.w);
            #pragma unroll
            for (int i = 0; i < 8; i++) {
                float4 p = *(const float4*)&Pt[(ty*8+i)*PADB + k4*4];
                fma2(acc[i][0], pk2(p.x,p.x), v0l); fma2(acc[i][1], pk2(p.x,p.x), v0h);
                fma2(acc[i][0], pk2(p.y,p.y), v1l); fma2(acc[i][1], pk2(p.y,p.y), v1h);
                fma2(acc[i][0], pk2(p.z,p.z), v2l); fma2(acc[i][1], pk2(p.z,p.z), v2h);
                fma2(acc[i][0], pk2(p.w,p.w), v3l); fma2(acc[i][1], pk2(p.w,p.w), v3h);
            }
        }
        __syncthreads();
    }

    #pragma unroll
    for (int i = 0; i < 8; i++) {
        float2 lo = up2(acc[i][0]), hi = up2(acc[i][1]);
        float4 r; r.x = lo.x; r.y = lo.y; r.z = hi.x; r.w = hi.y;
        *(float4*)&out[((size_t)bh*NSEQ + row0 + ty*8 + i)*DDIM + tx*4] = r;
    }
}

extern "C" void kernel_launch(void* const* d_in, const int* in_sizes, int n_in,
                              void* d_out, int out_size) {
    const float* q = (const float*)d_in[0];
    const float* k = (const float*)d_in[1];
    const float* v = (const float*)d_in[2];
    float* out = (float*)d_out;                                 // [B,H,N,D]
    float* attn_out = out + (size_t)B_ * H_ * NSEQ * DDIM;      // [B,H,N,N]

    const int smemA = (ROWS*NSEQ + ROWS*DDIM + 2*TILE_F) * 4 + ROWS*8 + ROWS*4;
    cudaFuncSetAttribute(sdpa_scores_kernel,
                         cudaFuncAttributeMaxDynamicSharedMemorySize, smemA);
    dim3 gridA(NSEQ / ROWS, BH);
    sdpa_scores_kernel<<<gridA, NTHREADS, smemA>>>(q, k, attn_out);

    const int smemB = 2 * STAGE_F * 4;
    cudaFuncSetAttribute(pv_kernel,
                         cudaFuncAttributeMaxDynamicSharedMemorySize, smemB);
    dim3 gridB(NSEQ / QB, BH);
    pv_kernel<<<gridB, 256, smemB>>>(attn_out, v, out);
}